// round 3
// baseline (speedup 1.0000x reference)
#include <cuda_runtime.h>

#define NB 8192
#define NQ 10
#define DEPTH 6

typedef unsigned long long ull;

// -------- scratch (no allocations allowed) --------
__device__ float  g_angles[NB * NQ];
__device__ float4 g_rot[DEPTH * NQ * 2];   // per gate: {u00r,u00i,u01r,u01i},{u10r,u10i,u11r,u11i}

// -------- packed f32x2 helpers --------
__device__ __forceinline__ ull pk(float lo, float hi) {
    ull r; asm("mov.b64 %0, {%1, %2};" : "=l"(r) : "f"(lo), "f"(hi)); return r;
}
__device__ __forceinline__ float plo(ull v) { return __uint_as_float((unsigned)v); }
__device__ __forceinline__ float phi_(ull v) { return __uint_as_float((unsigned)(v >> 32)); }
__device__ __forceinline__ ull swp(ull v) { return (v << 32) | (v >> 32); }
__device__ __forceinline__ ull ffma2(ull a, ull b, ull c) {
    ull d; asm("fma.rn.f32x2 %0, %1, %2, %3;" : "=l"(d) : "l"(a), "l"(b), "l"(c)); return d;
}
__device__ __forceinline__ ull fmul2(ull a, ull b) {
    ull d; asm("mul.rn.f32x2 %0, %1, %2;" : "=l"(d) : "l"(a), "l"(b)); return d;
}
__device__ __forceinline__ ull shfl64(ull v, int m) {
    unsigned lo = (unsigned)v, hi = (unsigned)(v >> 32);
    lo = __shfl_xor_sync(0xffffffffu, lo, m);
    hi = __shfl_xor_sync(0xffffffffu, hi, m);
    return ((ull)hi << 32) | lo;
}

// -------- gates --------
// qubit Q<5: bit Q of local index j; qubit Q>=5: bit (Q-5) of lane id.

template<int Q>
__device__ __forceinline__ void ry_gate(ull (&a)[32], float c, float s, int lane) {
    if constexpr (Q < 5) {
        constexpr int m = 1 << Q;
        ull cc = pk(c, c), ss = pk(s, s), ns = pk(-s, -s);
        #pragma unroll
        for (int j = 0; j < 32; j++) if (!(j & m)) {
            ull a0 = a[j], a1 = a[j | m];
            a[j]     = ffma2(cc, a0, fmul2(ns, a1));   // c*a0 - s*a1
            a[j | m] = ffma2(ss, a0, fmul2(cc, a1));   // s*a0 + c*a1
        }
    } else {
        constexpr int m = 1 << (Q - 5);
        float sb = (lane & m) ? s : -s;
        ull cc = pk(c, c), sg = pk(sb, sb);
        #pragma unroll
        for (int j = 0; j < 32; j++) {
            ull p = shfl64(a[j], m);
            a[j] = ffma2(cc, a[j], fmul2(sg, p));
        }
    }
}

template<int Q>
__device__ __forceinline__ void rot_gate(ull (&a)[32], const float4* up, int lane) {
    float4 ua = __ldg(up), ub = __ldg(up + 1);
    if constexpr (Q < 5) {
        constexpr int m = 1 << Q;
        ull u00r = pk(ua.x, ua.x), u00i = pk(-ua.y, ua.y);
        ull u01r = pk(ua.z, ua.z), u01i = pk(-ua.w, ua.w);
        ull u10r = pk(ub.x, ub.x), u10i = pk(-ub.y, ub.y);
        ull u11r = pk(ub.z, ub.z), u11i = pk(-ub.w, ub.w);
        #pragma unroll
        for (int j = 0; j < 32; j++) if (!(j & m)) {
            ull a0 = a[j], a1 = a[j | m];
            ull s0 = swp(a0), s1 = swp(a1);
            a[j]     = ffma2(u00r, a0, ffma2(u00i, s0, ffma2(u01r, a1, fmul2(u01i, s1))));
            a[j | m] = ffma2(u10r, a0, ffma2(u10i, s0, ffma2(u11r, a1, fmul2(u11i, s1))));
        }
    } else {
        constexpr int m = 1 << (Q - 5);
        bool b = (lane & m) != 0;
        float dr = b ? ub.z : ua.x, di = b ? ub.w : ua.y;   // diagonal element for my row
        float er = b ? ub.x : ua.z, ei = b ? ub.y : ua.w;   // off-diagonal element
        ull Dr = pk(dr, dr), Di = pk(-di, di), Or = pk(er, er), Oi = pk(-ei, ei);
        #pragma unroll
        for (int j = 0; j < 32; j++) {
            ull p = shfl64(a[j], m);
            ull sm = swp(a[j]), sp = swp(p);
            a[j] = ffma2(Dr, a[j], ffma2(Di, sm, ffma2(Or, p, fmul2(Oi, sp))));
        }
    }
}

template<int C, int T>
__device__ __forceinline__ void cnot_gate(ull (&a)[32], int lane) {
    if constexpr (C < 5 && T < 5) {
        constexpr int mc = 1 << C, mt = 1 << T;
        #pragma unroll
        for (int j = 0; j < 32; j++) if ((j & mc) && !(j & mt)) {
            ull t = a[j]; a[j] = a[j | mt]; a[j | mt] = t;   // pure register rename
        }
    } else if constexpr (C < 5 && T >= 5) {
        constexpr int mc = 1 << C, mt = 1 << (T - 5);
        #pragma unroll
        for (int j = 0; j < 32; j++) if (j & mc)
            a[j] = shfl64(a[j], mt);
    } else if constexpr (C >= 5 && T < 5) {
        constexpr int mc = 1 << (C - 5), mt = 1 << T;
        bool ctrl = (lane & mc) != 0;
        #pragma unroll
        for (int j = 0; j < 32; j++) if (!(j & mt)) {
            ull t0 = a[j], t1 = a[j | mt];
            a[j]      = ctrl ? t1 : t0;
            a[j | mt] = ctrl ? t0 : t1;
        }
    } else {
        constexpr int mc = 1 << (C - 5), mt = 1 << (T - 5);
        bool ctrl = (lane & mc) != 0;
        #pragma unroll
        for (int j = 0; j < 32; j++) {
            ull p = shfl64(a[j], mt);
            a[j] = ctrl ? p : a[j];
        }
    }
}

// -------- kernel 0: precompute Rot matrices (shared across batch) --------
__global__ void rot_prep(const float* __restrict__ w) {
    int t = threadIdx.x;
    if (t >= DEPTH * NQ) return;
    float ph = w[t * 3 + 0], th = w[t * 3 + 1], om = w[t * 3 + 2];
    float c, s, ca, sa, cb, sb;
    sincosf(0.5f * th, &s, &c);
    sincosf(0.5f * (ph + om), &sa, &ca);
    sincosf(0.5f * (ph - om), &sb, &cb);
    // U = [[ep*c, -conj(em)*s],[em*s, conj(ep)*c]], ep=e^{-ia}, em=e^{-ib}
    g_rot[t * 2 + 0] = make_float4(c * ca, -c * sa, -s * cb, -s * sb);
    g_rot[t * 2 + 1] = make_float4(s * cb, -s * sb,  c * ca,  c * sa);
}

// -------- kernel 1: angles = tanh(x @ Wp^T) * pi/2, one warp per sample --------
__global__ void __launch_bounds__(128) proj_kernel(const float* __restrict__ x,
                                                   const float* __restrict__ Wp) {
    int warp = (blockIdx.x * blockDim.x + threadIdx.x) >> 5;
    int lane = threadIdx.x & 31;
    const float4* xr = (const float4*)(x + (size_t)warp * 1024);
    const float4* w4 = (const float4*)Wp;
    float acc[NQ];
    #pragma unroll
    for (int q = 0; q < NQ; q++) acc[q] = 0.f;
    #pragma unroll
    for (int i = 0; i < 8; i++) {
        float4 xv = __ldg(&xr[i * 32 + lane]);
        #pragma unroll
        for (int q = 0; q < NQ; q++) {
            float4 wv = __ldg(&w4[q * 256 + i * 32 + lane]);
            acc[q] += xv.x * wv.x + xv.y * wv.y + xv.z * wv.z + xv.w * wv.w;
        }
    }
    #pragma unroll
    for (int q = 0; q < NQ; q++) {
        #pragma unroll
        for (int m = 16; m; m >>= 1) acc[q] += __shfl_xor_sync(0xffffffffu, acc[q], m);
    }
    if (lane == 0) {
        #pragma unroll
        for (int q = 0; q < NQ; q++)
            g_angles[warp * NQ + q] = tanhf(acc[q]) * 1.5707963267948966f;
    }
}

// -------- kernel 2: statevector simulation, one warp per sample --------
__global__ void __launch_bounds__(128) sim_kernel(const float* __restrict__ Wout,
                                                  const float* __restrict__ bout,
                                                  float* __restrict__ out) {
    int warp = (blockIdx.x * blockDim.x + threadIdx.x) >> 5;
    int lane = threadIdx.x & 31;
    const float* ang = g_angles + warp * NQ;

    ull a[32];
    #pragma unroll
    for (int j = 0; j < 32; j++) a[j] = 0ull;
    if (lane == 0) a[0] = pk(1.0f, 0.0f);

    // RY encoding
    #define RYQ(Q) { float t_ = 0.5f * __ldg(&ang[Q]); float s_, c_; __sincosf(t_, &s_, &c_); \
                     ry_gate<Q>(a, c_, s_, lane); }
    RYQ(0) RYQ(1) RYQ(2) RYQ(3) RYQ(4) RYQ(5) RYQ(6) RYQ(7) RYQ(8) RYQ(9)

    // StronglyEntanglingLayers: Rot on every qubit, then CNOT(i, (i+l+1)%10)
    #define ROTG(L, I) rot_gate<I>(a, &g_rot[((L) * 10 + (I)) * 2], lane);
    #define CXG(L, I)  cnot_gate<I, ((I) + (L) + 1) % 10>(a, lane);
    #define LAYER(L) \
        ROTG(L,0) ROTG(L,1) ROTG(L,2) ROTG(L,3) ROTG(L,4) \
        ROTG(L,5) ROTG(L,6) ROTG(L,7) ROTG(L,8) ROTG(L,9) \
        CXG(L,0) CXG(L,1) CXG(L,2) CXG(L,3) CXG(L,4) \
        CXG(L,5) CXG(L,6) CXG(L,7) CXG(L,8) CXG(L,9)
    LAYER(0) LAYER(1) LAYER(2) LAYER(3) LAYER(4) LAYER(5)

    // PauliZ expectations
    float s = 0.f, z0 = 0.f, z1 = 0.f, z2 = 0.f, z3 = 0.f, z4 = 0.f;
    #pragma unroll
    for (int j = 0; j < 32; j++) {
        float re = plo(a[j]), im = phi_(a[j]);
        float pr = re * re + im * im;
        s += pr;
        z0 += (j & 1)  ? -pr : pr;
        z1 += (j & 2)  ? -pr : pr;
        z2 += (j & 4)  ? -pr : pr;
        z3 += (j & 8)  ? -pr : pr;
        z4 += (j & 16) ? -pr : pr;
    }
    float z5 = (lane & 1)  ? -s : s;
    float z6 = (lane & 2)  ? -s : s;
    float z7 = (lane & 4)  ? -s : s;
    float z8 = (lane & 8)  ? -s : s;
    float z9 = (lane & 16) ? -s : s;
    #pragma unroll
    for (int m = 16; m; m >>= 1) {
        z0 += __shfl_xor_sync(0xffffffffu, z0, m);
        z1 += __shfl_xor_sync(0xffffffffu, z1, m);
        z2 += __shfl_xor_sync(0xffffffffu, z2, m);
        z3 += __shfl_xor_sync(0xffffffffu, z3, m);
        z4 += __shfl_xor_sync(0xffffffffu, z4, m);
        z5 += __shfl_xor_sync(0xffffffffu, z5, m);
        z6 += __shfl_xor_sync(0xffffffffu, z6, m);
        z7 += __shfl_xor_sync(0xffffffffu, z7, m);
        z8 += __shfl_xor_sync(0xffffffffu, z8, m);
        z9 += __shfl_xor_sync(0xffffffffu, z9, m);
    }

    // fused output head: out[b][c] = sum_q Wout[c][q]*z[q] + bout[c]
    if (lane < NQ) {
        const float* w = Wout + lane * NQ;
        float acc = __ldg(&bout[lane]);
        acc += __ldg(&w[0]) * z0; acc += __ldg(&w[1]) * z1;
        acc += __ldg(&w[2]) * z2; acc += __ldg(&w[3]) * z3;
        acc += __ldg(&w[4]) * z4; acc += __ldg(&w[5]) * z5;
        acc += __ldg(&w[6]) * z6; acc += __ldg(&w[7]) * z7;
        acc += __ldg(&w[8]) * z8; acc += __ldg(&w[9]) * z9;
        out[warp * NQ + lane] = acc;
    }
}

extern "C" void kernel_launch(void* const* d_in, const int* in_sizes, int n_in,
                              void* d_out, int out_size) {
    const float* x    = (const float*)d_in[0];   // (8192, 1024)
    const float* Wp   = (const float*)d_in[1];   // (10, 1024)
    const float* wts  = (const float*)d_in[2];   // (6, 10, 3)
    const float* Wout = (const float*)d_in[3];   // (10, 10)
    const float* bout = (const float*)d_in[4];   // (10,)
    float* out = (float*)d_out;                  // (8192, 10)

    rot_prep<<<1, 64>>>(wts);
    proj_kernel<<<NB / 4, 128>>>(x, Wp);         // 4 warps/block, 1 sample/warp
    sim_kernel<<<NB / 4, 128>>>(Wout, bout, out);
    (void)in_sizes; (void)n_in; (void)out_size;
}